// round 6
// baseline (speedup 1.0000x reference)
#include <cuda_runtime.h>

#define NN 50000
#define NE 800000
#define NG 1024
#define DIN 9
#define DD 64
#define SCAN_BLKS ((NN + 255) / 256)   // 196
#define GMN 64                          // nodes per layer block
#define AP  (GMN + 2)                   // agg pitch 66 (even, low-conflict)

// ---- scratch (static device globals) ----
__device__ float    g_ha [NN*DD];     // activations ping
__device__ float    g_hb [NN*DD];     // activations pong
__device__ float    g_aggx[NN*DIN];   // aggregated raw features (layer 0)
__device__ int      g_degi[NN];       // in-degree (no self loop)
__device__ float    g_dinv[NN];
__device__ int      g_rp  [NN];       // CSR row start
__device__ int      g_cur [NN];       // fill cursor
__device__ int2     g_ep  [NE];       // (src, bitcast norm)
__device__ int      g_bsum[256];
__device__ unsigned g_gmax[NG*DD];
__device__ float    g_gsum[NG*DD];
__device__ float    g_gcnt[NG];

__device__ __forceinline__ unsigned fkey(float f) {
    unsigned b = __float_as_uint(f);
    return (b & 0x80000000u) ? ~b : (b | 0x80000000u);
}
__device__ __forceinline__ float funkey(unsigned k) {
    unsigned b = (k & 0x80000000u) ? (k & 0x7FFFFFFFu) : ~k;
    return __uint_as_float(b);
}

__global__ void k_init() {
    int i = blockIdx.x * blockDim.x + threadIdx.x;
    if (i < NN) g_degi[i] = 0;
    if (i < NG*DD) { g_gmax[i] = 0u; g_gsum[i] = 0.0f; }
    if (i < NG) g_gcnt[i] = 0.0f;
}

__global__ void k_deg(const int4* __restrict__ dst4) {
    int e = blockIdx.x * blockDim.x + threadIdx.x;
    if (e >= NE/4) return;
    int4 d = dst4[e];
    atomicAdd(&g_degi[d.x], 1);
    atomicAdd(&g_degi[d.y], 1);
    atomicAdd(&g_degi[d.z], 1);
    atomicAdd(&g_degi[d.w], 1);
}

__global__ void k_scan1() {
    __shared__ int sh[256];
    int t = threadIdx.x, i = blockIdx.x * 256 + t;
    int v = (i < NN) ? g_degi[i] : 0;
    sh[t] = v; __syncthreads();
    #pragma unroll
    for (int off = 1; off < 256; off <<= 1) {
        int u = (t >= off) ? sh[t - off] : 0;
        __syncthreads();
        sh[t] += u; __syncthreads();
    }
    if (i < NN) g_rp[i] = sh[t] - v;
    if (t == 255) g_bsum[blockIdx.x] = sh[255];
}

// fused: per-block prefix of bsum + apply + cursor/dinv init
__global__ void k_scan3() {
    __shared__ int sh[256];
    int t = threadIdx.x;
    int v = (t < SCAN_BLKS) ? g_bsum[t] : 0;
    sh[t] = v; __syncthreads();
    #pragma unroll
    for (int off = 1; off < 256; off <<= 1) {
        int u = (t >= off) ? sh[t - off] : 0;
        __syncthreads();
        sh[t] += u; __syncthreads();
    }
    int boff = (blockIdx.x > 0) ? sh[blockIdx.x - 1] : 0;
    int i = blockIdx.x * 256 + t;
    if (i < NN) {
        g_rp[i] += boff;
        g_cur[i] = 0;
        g_dinv[i] = rsqrtf(1.0f + (float)g_degi[i]);
    }
}

__global__ void k_fill(const int4* __restrict__ src4, const int4* __restrict__ dst4) {
    int e = blockIdx.x * blockDim.x + threadIdx.x;
    if (e >= NE/4) return;
    int4 s = src4[e], d = dst4[e];
    int p;
    p = g_rp[d.x] + atomicAdd(&g_cur[d.x], 1);
    g_ep[p] = make_int2(s.x, __float_as_int(g_dinv[s.x] * g_dinv[d.x]));
    p = g_rp[d.y] + atomicAdd(&g_cur[d.y], 1);
    g_ep[p] = make_int2(s.y, __float_as_int(g_dinv[s.y] * g_dinv[d.y]));
    p = g_rp[d.z] + atomicAdd(&g_cur[d.z], 1);
    g_ep[p] = make_int2(s.z, __float_as_int(g_dinv[s.z] * g_dinv[d.z]));
    p = g_rp[d.w] + atomicAdd(&g_cur[d.w], 1);
    g_ep[p] = make_int2(s.w, __float_as_int(g_dinv[s.w] * g_dinv[d.w]));
}

// layer-0 aggregation over raw fp32 features (9 dims), 16 lanes/node, 2-way unroll
__global__ void k_gather9(const float* __restrict__ x) {
    int t = blockIdx.x * blockDim.x + threadIdx.x;
    int n = t >> 4, c = t & 15;
    if (n >= NN || c >= DIN) return;
    int rp = g_rp[n], dg = g_degi[n];
    float dn = g_dinv[n];
    float a0 = dn * dn * x[n*DIN + c];
    float a1 = 0.0f;
    int j = 0;
    for (; j + 2 <= dg; j += 2) {
        int2 p0 = g_ep[rp + j];
        int2 p1 = g_ep[rp + j + 1];
        a0 += __int_as_float(p0.y) * x[p0.x*DIN + c];
        a1 += __int_as_float(p1.y) * x[p1.x*DIN + c];
    }
    if (j < dg) {
        int2 p0 = g_ep[rp + j];
        a0 += __int_as_float(p0.y) * x[p0.x*DIN + c];
    }
    g_aggx[n*DIN + c] = a0 + a1;
}

// h0 = tanh(aggx @ W0 + b0); 8 nodes/block, lane computes 2 cols
__global__ void k_gemm0f(const float* __restrict__ W, const float* __restrict__ b) {
    __shared__ float Ws[DIN*DD];
    __shared__ float axs[8][DIN];
    int tid = threadIdx.x;
    for (int i = tid; i < DIN*DD; i += 256) Ws[i] = W[i];
    int nb = blockIdx.x * 8;
    if (tid < 8*DIN) {
        int r = tid / DIN, k = tid % DIN, n = nb + r;
        axs[r][k] = (n < NN) ? g_aggx[n*DIN + k] : 0.0f;
    }
    __syncthreads();
    int r = tid >> 5, l = tid & 31;
    int n = nb + r;
    if (n >= NN) return;
    int c0 = 2*l, c1 = 2*l + 1;
    float s0 = b[c0], s1 = b[c1];
    #pragma unroll
    for (int k = 0; k < DIN; k++) {
        float a = axs[r][k];
        s0 += a * Ws[k*DD + c0];
        s1 += a * Ws[k*DD + c1];
    }
    *reinterpret_cast<float2*>(&g_ha[n*DD + c0]) = make_float2(tanhf(s0), tanhf(s1));
}

// ---- fused layer: agg = Â h_in  (warp-per-node gather into smem, transposed)
//                   h_out = tanh(agg @ W + b)   [register-blocked GEMM]
template <bool POOL, bool STORE>
__global__ void k_layer(const float* __restrict__ hin, float* __restrict__ hout,
                        const float* __restrict__ W, const float* __restrict__ b,
                        const int* __restrict__ batch) {
    __shared__ float Ws[DD*DD];      // 16 KB
    __shared__ float agg[DD][AP];    // [k][n], pitch 66 -> 16.9 KB
    int tid = threadIdx.x;
    #pragma unroll
    for (int i = 0; i < 16; i++) Ws[tid + i*256] = W[tid + i*256];

    int nb = blockIdx.x * GMN;
    int wid = tid >> 5, lane = tid & 31;
    const float2* hin2 = reinterpret_cast<const float2*>(hin);

    // ---- phase A: 8 warps x 8 nodes, warp-per-node CSR gather ----
    #pragma unroll 1
    for (int s = 0; s < 8; s++) {
        int nl = wid * 8 + s;
        int n = nb + nl;
        float ax = 0.0f, ay = 0.0f;
        if (n < NN) {
            int rp = g_rp[n], dg = g_degi[n];
            float dn = g_dinv[n];
            float2 self = hin2[n*32 + lane];
            float d2 = dn * dn;
            ax = d2 * self.x; ay = d2 * self.y;
            int j = 0;
            for (; j + 4 <= dg; j += 4) {
                int2 p0 = g_ep[rp + j + 0];
                int2 p1 = g_ep[rp + j + 1];
                int2 p2 = g_ep[rp + j + 2];
                int2 p3 = g_ep[rp + j + 3];
                float2 v0 = hin2[p0.x*32 + lane];
                float2 v1 = hin2[p1.x*32 + lane];
                float2 v2 = hin2[p2.x*32 + lane];
                float2 v3 = hin2[p3.x*32 + lane];
                ax += __int_as_float(p0.y)*v0.x; ay += __int_as_float(p0.y)*v0.y;
                ax += __int_as_float(p1.y)*v1.x; ay += __int_as_float(p1.y)*v1.y;
                ax += __int_as_float(p2.y)*v2.x; ay += __int_as_float(p2.y)*v2.y;
                ax += __int_as_float(p3.y)*v3.x; ay += __int_as_float(p3.y)*v3.y;
            }
            for (; j < dg; j++) {
                int2 p0 = g_ep[rp + j];
                float2 v0 = hin2[p0.x*32 + lane];
                ax += __int_as_float(p0.y)*v0.x; ay += __int_as_float(p0.y)*v0.y;
            }
        }
        agg[2*lane    ][nl] = ax;
        agg[2*lane + 1][nl] = ay;
    }
    __syncthreads();

    // ---- phase B: register-blocked GEMM, thread = 2 nodes x 8 cols ----
    int q  = tid & 7;
    int rg = tid >> 3;
    int n0 = 2*rg;
    float acc0[8] = {0,0,0,0,0,0,0,0};
    float acc1[8] = {0,0,0,0,0,0,0,0};
    #pragma unroll
    for (int k = 0; k < DD; k++) {
        float2 h2 = *reinterpret_cast<const float2*>(&agg[k][n0]);
        const float4* wr = reinterpret_cast<const float4*>(&Ws[k*DD + q*8]);
        float4 w0 = wr[0], w1 = wr[1];
        acc0[0] += h2.x*w0.x; acc0[1] += h2.x*w0.y; acc0[2] += h2.x*w0.z; acc0[3] += h2.x*w0.w;
        acc0[4] += h2.x*w1.x; acc0[5] += h2.x*w1.y; acc0[6] += h2.x*w1.z; acc0[7] += h2.x*w1.w;
        acc1[0] += h2.y*w0.x; acc1[1] += h2.y*w0.y; acc1[2] += h2.y*w0.z; acc1[3] += h2.y*w0.w;
        acc1[4] += h2.y*w1.x; acc1[5] += h2.y*w1.y; acc1[6] += h2.y*w1.z; acc1[7] += h2.y*w1.w;
    }
    float4 bb0 = reinterpret_cast<const float4*>(b)[q*2];
    float4 bb1 = reinterpret_cast<const float4*>(b)[q*2 + 1];
    float r0[8], r1[8];
    r0[0]=tanhf(acc0[0]+bb0.x); r0[1]=tanhf(acc0[1]+bb0.y); r0[2]=tanhf(acc0[2]+bb0.z); r0[3]=tanhf(acc0[3]+bb0.w);
    r0[4]=tanhf(acc0[4]+bb1.x); r0[5]=tanhf(acc0[5]+bb1.y); r0[6]=tanhf(acc0[6]+bb1.z); r0[7]=tanhf(acc0[7]+bb1.w);
    r1[0]=tanhf(acc1[0]+bb0.x); r1[1]=tanhf(acc1[1]+bb0.y); r1[2]=tanhf(acc1[2]+bb0.z); r1[3]=tanhf(acc1[3]+bb0.w);
    r1[4]=tanhf(acc1[4]+bb1.x); r1[5]=tanhf(acc1[5]+bb1.y); r1[6]=tanhf(acc1[6]+bb1.z); r1[7]=tanhf(acc1[7]+bb1.w);

    int gn0 = nb + n0;
    if (STORE) {
        if (gn0 < NN) {
            float4* o = reinterpret_cast<float4*>(&hout[gn0*DD + q*8]);
            o[0] = make_float4(r0[0], r0[1], r0[2], r0[3]);
            o[1] = make_float4(r0[4], r0[5], r0[6], r0[7]);
        }
        if (gn0 + 1 < NN) {
            float4* o = reinterpret_cast<float4*>(&hout[(gn0+1)*DD + q*8]);
            o[0] = make_float4(r1[0], r1[1], r1[2], r1[3]);
            o[1] = make_float4(r1[4], r1[5], r1[6], r1[7]);
        }
    }
    if (POOL) {
        if (gn0 < NN) {
            int g = batch[gn0];
            int base = g*DD + q*8;
            #pragma unroll
            for (int k = 0; k < 8; k++) {
                atomicMax(&g_gmax[base + k], fkey(r0[k]));
                atomicAdd(&g_gsum[base + k], r0[k]);
            }
            if (q == 0) atomicAdd(&g_gcnt[g], 1.0f);
        }
        if (gn0 + 1 < NN) {
            int g = batch[gn0 + 1];
            int base = g*DD + q*8;
            #pragma unroll
            for (int k = 0; k < 8; k++) {
                atomicMax(&g_gmax[base + k], fkey(r1[k]));
                atomicAdd(&g_gsum[base + k], r1[k]);
            }
            if (q == 0) atomicAdd(&g_gcnt[g], 1.0f);
        }
    }
}

// warp-per-graph output head
__global__ void k_out(const float* __restrict__ Wout, const float* __restrict__ bout,
                      float* __restrict__ out) {
    int g = (blockIdx.x * blockDim.x + threadIdx.x) >> 5;
    int lane = threadIdx.x & 31;
    if (g >= NG) return;
    float cnt = fmaxf(g_gcnt[g], 1.0f);
    float s = 0.0f;
    #pragma unroll
    for (int d = lane; d < DD; d += 32) {
        s += funkey(g_gmax[g*DD + d]) * Wout[d]
           + (g_gsum[g*DD + d] / cnt) * Wout[DD + d];
    }
    #pragma unroll
    for (int o = 16; o > 0; o >>= 1) s += __shfl_down_sync(0xFFFFFFFFu, s, o);
    if (lane == 0) out[g] = s + bout[0];
}

extern "C" void kernel_launch(void* const* d_in, const int* in_sizes, int n_in,
                              void* d_out, int out_size) {
    const float* x     = (const float*)d_in[0];
    const int*   eidx  = (const int*)  d_in[1];
    const int*   batch = (const int*)  d_in[2];
    const float* W0 = (const float*)d_in[3];  const float* b0 = (const float*)d_in[4];
    const float* W1 = (const float*)d_in[5];  const float* b1 = (const float*)d_in[6];
    const float* W2 = (const float*)d_in[7];  const float* b2 = (const float*)d_in[8];
    const float* W3 = (const float*)d_in[9];  const float* b3 = (const float*)d_in[10];
    const float* Wout = (const float*)d_in[11];
    const float* bout = (const float*)d_in[12];
    float* out = (float*)d_out;

    const int* src = eidx;
    const int* dst = eidx + NE;

    // ---- CSR build ----
    k_init <<<(NG*DD + 255) / 256, 256>>>();
    k_deg  <<<(NE/4 + 255) / 256, 256>>>((const int4*)dst);
    k_scan1<<<SCAN_BLKS, 256>>>();
    k_scan3<<<SCAN_BLKS, 256>>>();
    k_fill <<<(NE/4 + 255) / 256, 256>>>((const int4*)src, (const int4*)dst);

    const int g9_blocks = (NN * 16 + 255) / 256;   // 3125
    const int ly_blocks = (NN + GMN - 1) / GMN;    // 782

    float* hout0;
    cudaGetSymbolAddress((void**)&hout0, g_hb);
    float* ha;
    cudaGetSymbolAddress((void**)&ha, g_ha);

    // layer 0: aggregate raw features, then transform -> g_ha
    k_gather9<<<g9_blocks, 256>>>(x);
    k_gemm0f <<<(NN + 7) / 8, 256>>>(W0, b0);
    // layers 1-3 fused (aggregate-then-transform), ping-pong
    k_layer<false, true ><<<ly_blocks, 256>>>(ha,    hout0, W1, b1, batch);
    k_layer<false, true ><<<ly_blocks, 256>>>(hout0, ha,    W2, b2, batch);
    k_layer<true,  false><<<ly_blocks, 256>>>(ha,    hout0, W3, b3, batch);

    k_out<<<(NG*32 + 255) / 256, 256>>>(Wout, bout, out);
}

// round 7
// speedup vs baseline: 1.1754x; 1.1754x over previous
#include <cuda_runtime.h>
#include <cuda_fp16.h>

#define NN 50000
#define NE 800000
#define NG 1024
#define DIN 9
#define DD 64
#define SCAN_BLKS ((NN + 255) / 256)   // 196
#define GMN 64                          // nodes per gemm64 block

// ---- scratch (static device globals) ----
__device__ __half2  g_h2 [NN*32];     // activations (post-tanh), fp16
__device__ __half2  g_hw2[NN*32];     // h @ W, fp16
__device__ float    g_aggx[NN*DIN];   // aggregated raw features (layer 0)
__device__ int      g_degi[NN];       // in-degree (no self loop)
__device__ float    g_dinv[NN];
__device__ int      g_rp  [NN];       // CSR row start
__device__ int      g_cur [NN];       // fill cursor
__device__ int2     g_ep  [NE];       // (src, bitcast norm)
__device__ int      g_bsum[256];
__device__ unsigned g_gmax[NG*DD];
__device__ float    g_gsum[NG*DD];
__device__ float    g_gcnt[NG];

__device__ __forceinline__ unsigned fkey(float f) {
    unsigned b = __float_as_uint(f);
    return (b & 0x80000000u) ? ~b : (b | 0x80000000u);
}
__device__ __forceinline__ float funkey(unsigned k) {
    unsigned b = (k & 0x80000000u) ? (k & 0x7FFFFFFFu) : ~k;
    return __uint_as_float(b);
}

__global__ void k_init() {
    int i = blockIdx.x * blockDim.x + threadIdx.x;
    if (i < NN) g_degi[i] = 0;
    if (i < NG*DD) { g_gmax[i] = 0u; g_gsum[i] = 0.0f; }
    if (i < NG) g_gcnt[i] = 0.0f;
}

__global__ void k_deg(const int4* __restrict__ dst4) {
    int e = blockIdx.x * blockDim.x + threadIdx.x;
    if (e >= NE/4) return;
    int4 d = dst4[e];
    atomicAdd(&g_degi[d.x], 1);
    atomicAdd(&g_degi[d.y], 1);
    atomicAdd(&g_degi[d.z], 1);
    atomicAdd(&g_degi[d.w], 1);
}

// shuffle-based per-block inclusive scan -> rp (exclusive), block sums
__global__ void k_scan1() {
    __shared__ int wsum[8], wpre[8];
    int t = threadIdx.x, i = blockIdx.x * 256 + t;
    int lane = t & 31, w = t >> 5;
    int v = (i < NN) ? g_degi[i] : 0;
    int s = v;
    #pragma unroll
    for (int off = 1; off < 32; off <<= 1) {
        int u = __shfl_up_sync(0xFFFFFFFFu, s, off);
        if (lane >= off) s += u;
    }
    if (lane == 31) wsum[w] = s;
    __syncthreads();
    if (t == 0) {
        int a = 0;
        #pragma unroll
        for (int j = 0; j < 8; j++) { wpre[j] = a; a += wsum[j]; }
    }
    __syncthreads();
    int incl = s + wpre[w];
    if (i < NN) g_rp[i] = incl - v;
    if (t == 255) g_bsum[blockIdx.x] = incl;
}

// per-block re-scan of bsum (shuffle) + apply + cursor/dinv init
__global__ void k_scan3() {
    __shared__ int wsum[8], wpre[8], allincl[256];
    int t = threadIdx.x;
    int lane = t & 31, w = t >> 5;
    int v = (t < SCAN_BLKS) ? g_bsum[t] : 0;
    int s = v;
    #pragma unroll
    for (int off = 1; off < 32; off <<= 1) {
        int u = __shfl_up_sync(0xFFFFFFFFu, s, off);
        if (lane >= off) s += u;
    }
    if (lane == 31) wsum[w] = s;
    __syncthreads();
    if (t == 0) {
        int a = 0;
        #pragma unroll
        for (int j = 0; j < 8; j++) { wpre[j] = a; a += wsum[j]; }
    }
    __syncthreads();
    allincl[t] = s + wpre[w];
    __syncthreads();
    int boff = (blockIdx.x > 0) ? allincl[blockIdx.x - 1] : 0;
    int i = blockIdx.x * 256 + t;
    if (i < NN) {
        g_rp[i] += boff;
        g_cur[i] = 0;
        g_dinv[i] = rsqrtf(1.0f + (float)g_degi[i]);
    }
}

__global__ void k_fill(const int4* __restrict__ src4, const int4* __restrict__ dst4) {
    int e = blockIdx.x * blockDim.x + threadIdx.x;
    if (e >= NE/4) return;
    int4 s = src4[e], d = dst4[e];
    int p;
    p = g_rp[d.x] + atomicAdd(&g_cur[d.x], 1);
    g_ep[p] = make_int2(s.x, __float_as_int(g_dinv[s.x] * g_dinv[d.x]));
    p = g_rp[d.y] + atomicAdd(&g_cur[d.y], 1);
    g_ep[p] = make_int2(s.y, __float_as_int(g_dinv[s.y] * g_dinv[d.y]));
    p = g_rp[d.z] + atomicAdd(&g_cur[d.z], 1);
    g_ep[p] = make_int2(s.z, __float_as_int(g_dinv[s.z] * g_dinv[d.z]));
    p = g_rp[d.w] + atomicAdd(&g_cur[d.w], 1);
    g_ep[p] = make_int2(s.w, __float_as_int(g_dinv[s.w] * g_dinv[d.w]));
}

// layer-0 aggregation over raw fp32 features (9 dims), 16 lanes/node, 2-way unroll
__global__ void k_gather9(const float* __restrict__ x) {
    int t = blockIdx.x * blockDim.x + threadIdx.x;
    int n = t >> 4, c = t & 15;
    if (n >= NN || c >= DIN) return;
    int rp = g_rp[n], dg = g_degi[n];
    float dn = g_dinv[n];
    float a0 = dn * dn * x[n*DIN + c];
    float a1 = 0.0f;
    int j = 0;
    for (; j + 2 <= dg; j += 2) {
        int2 p0 = g_ep[rp + j];
        int2 p1 = g_ep[rp + j + 1];
        a0 += __int_as_float(p0.y) * x[p0.x*DIN + c];
        a1 += __int_as_float(p1.y) * x[p1.x*DIN + c];
    }
    if (j < dg) {
        int2 p0 = g_ep[rp + j];
        a0 += __int_as_float(p0.y) * x[p0.x*DIN + c];
    }
    g_aggx[n*DIN + c] = a0 + a1;
}

// h0 = tanh(aggx @ W0 + b0) -> fp16; 8 nodes/block, lane computes 2 cols
__global__ void k_gemm0f(const float* __restrict__ W, const float* __restrict__ b) {
    __shared__ float Ws[DIN*DD];
    __shared__ float axs[8][DIN];
    int tid = threadIdx.x;
    for (int i = tid; i < DIN*DD; i += 256) Ws[i] = W[i];
    int nb = blockIdx.x * 8;
    if (tid < 8*DIN) {
        int r = tid / DIN, k = tid % DIN, n = nb + r;
        axs[r][k] = (n < NN) ? g_aggx[n*DIN + k] : 0.0f;
    }
    __syncthreads();
    int r = tid >> 5, l = tid & 31;
    int n = nb + r;
    if (n >= NN) return;
    int c0 = 2*l, c1 = 2*l + 1;
    float s0 = b[c0], s1 = b[c1];
    #pragma unroll
    for (int k = 0; k < DIN; k++) {
        float a = axs[r][k];
        s0 += a * Ws[k*DD + c0];
        s1 += a * Ws[k*DD + c1];
    }
    g_h2[n*32 + l] = __floats2half2_rn(tanhf(s0), tanhf(s1));
}

// hw = h @ W: fp16 storage, fp32 math. 64 nodes/block, thread = 2 rows x 8 cols.
__global__ void k_gemm64(const float* __restrict__ W) {
    __shared__ float Ws[DD*DD];          // 16 KB
    __shared__ float hs[DD][GMN + 4];    // transposed [k][n], 17.4 KB
    int tid = threadIdx.x;
    #pragma unroll
    for (int i = 0; i < 16; i++) Ws[tid + i*256] = W[tid + i*256];
    int nb = blockIdx.x * GMN;
    #pragma unroll
    for (int i = 0; i < 8; i++) {
        int idx = tid + i*256;           // 0..2047 : (node, half2-col)
        int n = idx >> 5, k2 = idx & 31;
        int gn = nb + n;
        float2 f = (gn < NN) ? __half22float2(g_h2[gn*32 + k2])
                             : make_float2(0.0f, 0.0f);
        hs[2*k2    ][n] = f.x;
        hs[2*k2 + 1][n] = f.y;
    }
    __syncthreads();
    int q  = tid & 7;
    int rg = tid >> 3;
    int n0 = 2*rg;
    float acc0[8] = {0,0,0,0,0,0,0,0};
    float acc1[8] = {0,0,0,0,0,0,0,0};
    #pragma unroll
    for (int k = 0; k < DD; k++) {
        float2 h2 = *reinterpret_cast<const float2*>(&hs[k][n0]);
        const float4* wr = reinterpret_cast<const float4*>(&Ws[k*DD + q*8]);
        float4 w0 = wr[0], w1 = wr[1];
        acc0[0] += h2.x*w0.x; acc0[1] += h2.x*w0.y; acc0[2] += h2.x*w0.z; acc0[3] += h2.x*w0.w;
        acc0[4] += h2.x*w1.x; acc0[5] += h2.x*w1.y; acc0[6] += h2.x*w1.z; acc0[7] += h2.x*w1.w;
        acc1[0] += h2.y*w0.x; acc1[1] += h2.y*w0.y; acc1[2] += h2.y*w0.z; acc1[3] += h2.y*w0.w;
        acc1[4] += h2.y*w1.x; acc1[5] += h2.y*w1.y; acc1[6] += h2.y*w1.z; acc1[7] += h2.y*w1.w;
    }
    int gn0 = nb + n0;
    if (gn0 < NN) {
        __half2 o[4];
        #pragma unroll
        for (int j = 0; j < 4; j++) o[j] = __floats2half2_rn(acc0[2*j], acc0[2*j+1]);
        *reinterpret_cast<uint4*>(&g_hw2[gn0*32 + q*4]) = *reinterpret_cast<uint4*>(o);
    }
    if (gn0 + 1 < NN) {
        __half2 o[4];
        #pragma unroll
        for (int j = 0; j < 4; j++) o[j] = __floats2half2_rn(acc1[2*j], acc1[2*j+1]);
        *reinterpret_cast<uint4*>(&g_hw2[(gn0+1)*32 + q*4]) = *reinterpret_cast<uint4*>(o);
    }
}

// CSR gather, warp-per-node: lane owns one half2 (LDG.32/edge/lane); fp32 accum
template <bool POOL>
__global__ void k_gather64(const float* __restrict__ b, const int* __restrict__ batch) {
    int n = (blockIdx.x * blockDim.x + threadIdx.x) >> 5;
    int lane = threadIdx.x & 31;
    if (n >= NN) return;
    int rp = g_rp[n], dg = g_degi[n];
    float dn = g_dinv[n];
    float2 self = __half22float2(g_hw2[n*32 + lane]);
    float d2 = dn * dn;
    float ax = d2 * self.x, ay = d2 * self.y;
    int j = 0;
    for (; j + 4 <= dg; j += 4) {
        int2 p0 = g_ep[rp + j + 0];
        int2 p1 = g_ep[rp + j + 1];
        int2 p2 = g_ep[rp + j + 2];
        int2 p3 = g_ep[rp + j + 3];
        __half2 h0 = g_hw2[p0.x*32 + lane];
        __half2 h1 = g_hw2[p1.x*32 + lane];
        __half2 h2 = g_hw2[p2.x*32 + lane];
        __half2 h3 = g_hw2[p3.x*32 + lane];
        float2 v0 = __half22float2(h0);
        float2 v1 = __half22float2(h1);
        float2 v2 = __half22float2(h2);
        float2 v3 = __half22float2(h3);
        ax += __int_as_float(p0.y)*v0.x; ay += __int_as_float(p0.y)*v0.y;
        ax += __int_as_float(p1.y)*v1.x; ay += __int_as_float(p1.y)*v1.y;
        ax += __int_as_float(p2.y)*v2.x; ay += __int_as_float(p2.y)*v2.y;
        ax += __int_as_float(p3.y)*v3.x; ay += __int_as_float(p3.y)*v3.y;
    }
    for (; j < dg; j++) {
        int2 p0 = g_ep[rp + j];
        float2 v0 = __half22float2(g_hw2[p0.x*32 + lane]);
        ax += __int_as_float(p0.y)*v0.x; ay += __int_as_float(p0.y)*v0.y;
    }
    float2 bb = reinterpret_cast<const float2*>(b)[lane];
    float rx = tanhf(ax + bb.x);
    float ry = tanhf(ay + bb.y);
    g_h2[n*32 + lane] = __floats2half2_rn(rx, ry);
    if (POOL) {
        int g = batch[n];
        int base = g*DD + 2*lane;
        atomicMax(&g_gmax[base + 0], fkey(rx));
        atomicMax(&g_gmax[base + 1], fkey(ry));
        atomicAdd(&g_gsum[base + 0], rx);
        atomicAdd(&g_gsum[base + 1], ry);
        if (lane == 0) atomicAdd(&g_gcnt[g], 1.0f);
    }
}

// warp-per-graph output head
__global__ void k_out(const float* __restrict__ Wout, const float* __restrict__ bout,
                      float* __restrict__ out) {
    int g = (blockIdx.x * blockDim.x + threadIdx.x) >> 5;
    int lane = threadIdx.x & 31;
    if (g >= NG) return;
    float cnt = fmaxf(g_gcnt[g], 1.0f);
    float s = 0.0f;
    #pragma unroll
    for (int d = lane; d < DD; d += 32) {
        s += funkey(g_gmax[g*DD + d]) * Wout[d]
           + (g_gsum[g*DD + d] / cnt) * Wout[DD + d];
    }
    #pragma unroll
    for (int o = 16; o > 0; o >>= 1) s += __shfl_down_sync(0xFFFFFFFFu, s, o);
    if (lane == 0) out[g] = s + bout[0];
}

extern "C" void kernel_launch(void* const* d_in, const int* in_sizes, int n_in,
                              void* d_out, int out_size) {
    const float* x     = (const float*)d_in[0];
    const int*   eidx  = (const int*)  d_in[1];
    const int*   batch = (const int*)  d_in[2];
    const float* W0 = (const float*)d_in[3];  const float* b0 = (const float*)d_in[4];
    const float* W1 = (const float*)d_in[5];  const float* b1 = (const float*)d_in[6];
    const float* W2 = (const float*)d_in[7];  const float* b2 = (const float*)d_in[8];
    const float* W3 = (const float*)d_in[9];  const float* b3 = (const float*)d_in[10];
    const float* Wout = (const float*)d_in[11];
    const float* bout = (const float*)d_in[12];
    float* out = (float*)d_out;

    const int* src = eidx;
    const int* dst = eidx + NE;

    // ---- CSR build ----
    k_init <<<(NG*DD + 255) / 256, 256>>>();
    k_deg  <<<(NE/4 + 255) / 256, 256>>>((const int4*)dst);
    k_scan1<<<SCAN_BLKS, 256>>>();
    k_scan3<<<SCAN_BLKS, 256>>>();
    k_fill <<<(NE/4 + 255) / 256, 256>>>((const int4*)src, (const int4*)dst);

    const int g9_blocks  = (NN * 16 + 255) / 256;  // 3125
    const int g64_blocks = (NN * 32 + 255) / 256;  // 6250 (warp per node)
    const int gm_blocks  = (NN + GMN - 1) / GMN;   // 782

    // layer 0: aggregate-then-transform
    k_gather9<<<g9_blocks, 256>>>(x);
    k_gemm0f <<<(NN + 7) / 8, 256>>>(W0, b0);
    // layers 1-3
    k_gemm64  <<<gm_blocks, 256>>>(W1);
    k_gather64<false><<<g64_blocks, 256>>>(b1, batch);
    k_gemm64  <<<gm_blocks, 256>>>(W2);
    k_gather64<false><<<g64_blocks, 256>>>(b2, batch);
    k_gemm64  <<<gm_blocks, 256>>>(W3);
    k_gather64<true> <<<g64_blocks, 256>>>(b3, batch);

    k_out<<<(NG*32 + 255) / 256, 256>>>(Wout, bout, out);
}

// round 8
// speedup vs baseline: 1.2466x; 1.0606x over previous
#include <cuda_runtime.h>
#include <cuda_fp16.h>

#define NN 50000
#define NE 800000
#define NG 1024
#define DIN 9
#define DD 64
#define SCAN_BLKS ((NN + 255) / 256)   // 196
#define GMN 64                          // nodes per gemm64 block
#define EPAD (NE + 4*NN)                // padded edge array size

// ---- scratch (static device globals) ----
__device__ __half2  g_h2 [NN*32];        // activations (post-tanh), fp16
__device__ __half2  g_z2 [(NN+1)*32];    // z = dinv * (h @ W), fp16; row NN = 0
__device__ float    g_zx [(NN+1)*DIN];   // dinv * x ; row NN = 0
__device__ float    g_aggx[NN*DIN];      // layer-0 aggregate
__device__ int      g_degi[NN];          // in-degree (no self loop)
__device__ float    g_dinv[NN];
__device__ int      g_rp  [NN];          // padded CSR row start (4-aligned)
__device__ int      g_cur [NN];          // fill cursor
__device__ int      g_es  [EPAD];        // src indices, padded rows -> NN
__device__ int      g_bsum[256];
__device__ unsigned g_gmax[NG*DD];
__device__ float    g_gsum[NG*DD];
__device__ float    g_gcnt[NG];

__device__ __forceinline__ unsigned fkey(float f) {
    unsigned b = __float_as_uint(f);
    return (b & 0x80000000u) ? ~b : (b | 0x80000000u);
}
__device__ __forceinline__ float funkey(unsigned k) {
    unsigned b = (k & 0x80000000u) ? (k & 0x7FFFFFFFu) : ~k;
    return __uint_as_float(b);
}

__global__ void k_init() {
    int i = blockIdx.x * blockDim.x + threadIdx.x;
    if (i < NN) g_degi[i] = 0;
    if (i < NG*DD) { g_gmax[i] = 0u; g_gsum[i] = 0.0f; }
    if (i < NG) g_gcnt[i] = 0.0f;
    if (i < 32) g_z2[NN*32 + i] = __float2half2_rn(0.0f);   // dummy z row
    if (i < DIN) g_zx[NN*DIN + i] = 0.0f;                   // dummy zx row
}

__global__ void k_deg(const int4* __restrict__ dst4) {
    int e = blockIdx.x * blockDim.x + threadIdx.x;
    if (e >= NE/4) return;
    int4 d = dst4[e];
    atomicAdd(&g_degi[d.x], 1);
    atomicAdd(&g_degi[d.y], 1);
    atomicAdd(&g_degi[d.z], 1);
    atomicAdd(&g_degi[d.w], 1);
}

// shuffle scan of PADDED degree -> rp (exclusive), block sums
__global__ void k_scan1() {
    __shared__ int wsum[8], wpre[8];
    int t = threadIdx.x, i = blockIdx.x * 256 + t;
    int lane = t & 31, w = t >> 5;
    int v = (i < NN) ? ((g_degi[i] + 3) & ~3) : 0;
    int s = v;
    #pragma unroll
    for (int off = 1; off < 32; off <<= 1) {
        int u = __shfl_up_sync(0xFFFFFFFFu, s, off);
        if (lane >= off) s += u;
    }
    if (lane == 31) wsum[w] = s;
    __syncthreads();
    if (t == 0) {
        int a = 0;
        #pragma unroll
        for (int j = 0; j < 8; j++) { wpre[j] = a; a += wsum[j]; }
    }
    __syncthreads();
    int incl = s + wpre[w];
    if (i < NN) g_rp[i] = incl - v;
    if (t == 255) g_bsum[blockIdx.x] = incl;
}

// re-scan bsum + apply; also: cursor, dinv, zx = dinv*x, pad-slot fill
__global__ void k_scan3(const float* __restrict__ x) {
    __shared__ int wsum[8], wpre[8], allincl[256];
    int t = threadIdx.x;
    int lane = t & 31, w = t >> 5;
    int v = (t < SCAN_BLKS) ? g_bsum[t] : 0;
    int s = v;
    #pragma unroll
    for (int off = 1; off < 32; off <<= 1) {
        int u = __shfl_up_sync(0xFFFFFFFFu, s, off);
        if (lane >= off) s += u;
    }
    if (lane == 31) wsum[w] = s;
    __syncthreads();
    if (t == 0) {
        int a = 0;
        #pragma unroll
        for (int j = 0; j < 8; j++) { wpre[j] = a; a += wsum[j]; }
    }
    __syncthreads();
    allincl[t] = s + wpre[w];
    __syncthreads();
    int boff = (blockIdx.x > 0) ? allincl[blockIdx.x - 1] : 0;
    int i = blockIdx.x * 256 + t;
    if (i < NN) {
        int rp = g_rp[i] + boff;
        g_rp[i] = rp;
        g_cur[i] = 0;
        int dg = g_degi[i];
        float dv = rsqrtf(1.0f + (float)dg);
        g_dinv[i] = dv;
        #pragma unroll
        for (int k = 0; k < DIN; k++) g_zx[i*DIN + k] = dv * x[i*DIN + k];
        int pdg = (dg + 3) & ~3;
        for (int p = dg; p < pdg; p++) g_es[rp + p] = NN;   // pad -> dummy node
    }
}

__global__ void k_fill(const int4* __restrict__ src4, const int4* __restrict__ dst4) {
    int e = blockIdx.x * blockDim.x + threadIdx.x;
    if (e >= NE/4) return;
    int4 s = src4[e], d = dst4[e];
    g_es[g_rp[d.x] + atomicAdd(&g_cur[d.x], 1)] = s.x;
    g_es[g_rp[d.y] + atomicAdd(&g_cur[d.y], 1)] = s.y;
    g_es[g_rp[d.z] + atomicAdd(&g_cur[d.z], 1)] = s.z;
    g_es[g_rp[d.w] + atomicAdd(&g_cur[d.w], 1)] = s.w;
}

// layer-0: aggx[d] = dinv[d] * (zx[d] + sum zx[s]); 16 lanes/node (9 active)
__global__ void k_gather9() {
    int t = blockIdx.x * blockDim.x + threadIdx.x;
    int n = t >> 4, c = t & 15;
    if (n >= NN || c >= DIN) return;
    int rp = g_rp[n];
    int pdg = (g_degi[n] + 3) & ~3;
    float a0 = g_zx[n*DIN + c], a1 = 0.0f;
    const int4* sp = reinterpret_cast<const int4*>(&g_es[rp]);
    for (int it = 0; it < (pdg >> 2); it++) {
        int4 s = sp[it];
        a0 += g_zx[s.x*DIN + c];
        a1 += g_zx[s.y*DIN + c];
        a0 += g_zx[s.z*DIN + c];
        a1 += g_zx[s.w*DIN + c];
    }
    g_aggx[n*DIN + c] = g_dinv[n] * (a0 + a1);
}

// h0 = tanh(aggx @ W0 + b0) -> fp16; 8 nodes/block, lane computes 2 cols
__global__ void k_gemm0f(const float* __restrict__ W, const float* __restrict__ b) {
    __shared__ float Ws[DIN*DD];
    __shared__ float axs[8][DIN];
    int tid = threadIdx.x;
    for (int i = tid; i < DIN*DD; i += 256) Ws[i] = W[i];
    int nb = blockIdx.x * 8;
    if (tid < 8*DIN) {
        int r = tid / DIN, k = tid % DIN, n = nb + r;
        axs[r][k] = (n < NN) ? g_aggx[n*DIN + k] : 0.0f;
    }
    __syncthreads();
    int r = tid >> 5, l = tid & 31;
    int n = nb + r;
    if (n >= NN) return;
    int c0 = 2*l, c1 = 2*l + 1;
    float s0 = b[c0], s1 = b[c1];
    #pragma unroll
    for (int k = 0; k < DIN; k++) {
        float a = axs[r][k];
        s0 += a * Ws[k*DD + c0];
        s1 += a * Ws[k*DD + c1];
    }
    g_h2[n*32 + l] = __floats2half2_rn(tanhf(s0), tanhf(s1));
}

// z = dinv * (h @ W): fp16 storage, fp32 math; 64 nodes/block, 2 rows x 8 cols/thread
__global__ void k_gemm64(const float* __restrict__ W) {
    __shared__ float Ws[DD*DD];
    __shared__ float hs[DD][GMN + 4];
    int tid = threadIdx.x;
    #pragma unroll
    for (int i = 0; i < 16; i++) Ws[tid + i*256] = W[tid + i*256];
    int nb = blockIdx.x * GMN;
    #pragma unroll
    for (int i = 0; i < 8; i++) {
        int idx = tid + i*256;
        int n = idx >> 5, k2 = idx & 31;
        int gn = nb + n;
        float2 f = (gn < NN) ? __half22float2(g_h2[gn*32 + k2])
                             : make_float2(0.0f, 0.0f);
        hs[2*k2    ][n] = f.x;
        hs[2*k2 + 1][n] = f.y;
    }
    __syncthreads();
    int q  = tid & 7;
    int rg = tid >> 3;
    int n0 = 2*rg;
    float acc0[8] = {0,0,0,0,0,0,0,0};
    float acc1[8] = {0,0,0,0,0,0,0,0};
    #pragma unroll
    for (int k = 0; k < DD; k++) {
        float2 h2 = *reinterpret_cast<const float2*>(&hs[k][n0]);
        const float4* wr = reinterpret_cast<const float4*>(&Ws[k*DD + q*8]);
        float4 w0 = wr[0], w1 = wr[1];
        acc0[0] += h2.x*w0.x; acc0[1] += h2.x*w0.y; acc0[2] += h2.x*w0.z; acc0[3] += h2.x*w0.w;
        acc0[4] += h2.x*w1.x; acc0[5] += h2.x*w1.y; acc0[6] += h2.x*w1.z; acc0[7] += h2.x*w1.w;
        acc1[0] += h2.y*w0.x; acc1[1] += h2.y*w0.y; acc1[2] += h2.y*w0.z; acc1[3] += h2.y*w0.w;
        acc1[4] += h2.y*w1.x; acc1[5] += h2.y*w1.y; acc1[6] += h2.y*w1.z; acc1[7] += h2.y*w1.w;
    }
    int gn0 = nb + n0;
    if (gn0 < NN) {
        float dv = g_dinv[gn0];
        __half2 o[4];
        #pragma unroll
        for (int j = 0; j < 4; j++) o[j] = __floats2half2_rn(dv*acc0[2*j], dv*acc0[2*j+1]);
        *reinterpret_cast<uint4*>(&g_z2[gn0*32 + q*4]) = *reinterpret_cast<uint4*>(o);
    }
    if (gn0 + 1 < NN) {
        float dv = g_dinv[gn0 + 1];
        __half2 o[4];
        #pragma unroll
        for (int j = 0; j < 4; j++) o[j] = __floats2half2_rn(dv*acc1[2*j], dv*acc1[2*j+1]);
        *reinterpret_cast<uint4*>(&g_z2[(gn0+1)*32 + q*4]) = *reinterpret_cast<uint4*>(o);
    }
}

// gather: h_out[d] = tanh(dinv[d]*(z[d] + sum z[s]) + b); warp-per-node, int4 idx
template <bool POOL>
__global__ void k_gather64(const float* __restrict__ b, const int* __restrict__ batch) {
    int n = (blockIdx.x * blockDim.x + threadIdx.x) >> 5;
    int lane = threadIdx.x & 31;
    if (n >= NN) return;
    int rp = g_rp[n];
    int pdg = (g_degi[n] + 3) & ~3;
    float2 self = __half22float2(g_z2[n*32 + lane]);
    float ax = self.x, ay = self.y;
    const int4* sp = reinterpret_cast<const int4*>(&g_es[rp]);
    int it = 0, iters = pdg >> 2;
    for (; it + 2 <= iters; it += 2) {      // 8 edges in flight
        int4 s0 = sp[it], s1 = sp[it + 1];
        float2 v0 = __half22float2(g_z2[s0.x*32 + lane]);
        float2 v1 = __half22float2(g_z2[s0.y*32 + lane]);
        float2 v2 = __half22float2(g_z2[s0.z*32 + lane]);
        float2 v3 = __half22float2(g_z2[s0.w*32 + lane]);
        float2 v4 = __half22float2(g_z2[s1.x*32 + lane]);
        float2 v5 = __half22float2(g_z2[s1.y*32 + lane]);
        float2 v6 = __half22float2(g_z2[s1.z*32 + lane]);
        float2 v7 = __half22float2(g_z2[s1.w*32 + lane]);
        ax += v0.x + v1.x; ay += v0.y + v1.y;
        ax += v2.x + v3.x; ay += v2.y + v3.y;
        ax += v4.x + v5.x; ay += v4.y + v5.y;
        ax += v6.x + v7.x; ay += v6.y + v7.y;
    }
    if (it < iters) {
        int4 s0 = sp[it];
        float2 v0 = __half22float2(g_z2[s0.x*32 + lane]);
        float2 v1 = __half22float2(g_z2[s0.y*32 + lane]);
        float2 v2 = __half22float2(g_z2[s0.z*32 + lane]);
        float2 v3 = __half22float2(g_z2[s0.w*32 + lane]);
        ax += v0.x + v1.x; ay += v0.y + v1.y;
        ax += v2.x + v3.x; ay += v2.y + v3.y;
    }
    float dv = g_dinv[n];
    float2 bb = reinterpret_cast<const float2*>(b)[lane];
    float rx = tanhf(dv*ax + bb.x);
    float ry = tanhf(dv*ay + bb.y);
    g_h2[n*32 + lane] = __floats2half2_rn(rx, ry);
    if (POOL) {
        int g = batch[n];
        int base = g*DD + 2*lane;
        atomicMax(&g_gmax[base + 0], fkey(rx));
        atomicMax(&g_gmax[base + 1], fkey(ry));
        atomicAdd(&g_gsum[base + 0], rx);
        atomicAdd(&g_gsum[base + 1], ry);
        if (lane == 0) atomicAdd(&g_gcnt[g], 1.0f);
    }
}

// warp-per-graph output head
__global__ void k_out(const float* __restrict__ Wout, const float* __restrict__ bout,
                      float* __restrict__ out) {
    int g = (blockIdx.x * blockDim.x + threadIdx.x) >> 5;
    int lane = threadIdx.x & 31;
    if (g >= NG) return;
    float cnt = fmaxf(g_gcnt[g], 1.0f);
    float s = 0.0f;
    #pragma unroll
    for (int d = lane; d < DD; d += 32) {
        s += funkey(g_gmax[g*DD + d]) * Wout[d]
           + (g_gsum[g*DD + d] / cnt) * Wout[DD + d];
    }
    #pragma unroll
    for (int o = 16; o > 0; o >>= 1) s += __shfl_down_sync(0xFFFFFFFFu, s, o);
    if (lane == 0) out[g] = s + bout[0];
}

extern "C" void kernel_launch(void* const* d_in, const int* in_sizes, int n_in,
                              void* d_out, int out_size) {
    const float* x     = (const float*)d_in[0];
    const int*   eidx  = (const int*)  d_in[1];
    const int*   batch = (const int*)  d_in[2];
    const float* W0 = (const float*)d_in[3];  const float* b0 = (const float*)d_in[4];
    const float* W1 = (const float*)d_in[5];  const float* b1 = (const float*)d_in[6];
    const float* W2 = (const float*)d_in[7];  const float* b2 = (const float*)d_in[8];
    const float* W3 = (const float*)d_in[9];  const float* b3 = (const float*)d_in[10];
    const float* Wout = (const float*)d_in[11];
    const float* bout = (const float*)d_in[12];
    float* out = (float*)d_out;

    const int* src = eidx;
    const int* dst = eidx + NE;

    // ---- CSR build (padded rows, index-only edges) ----
    k_init <<<(NG*DD + 255) / 256, 256>>>();
    k_deg  <<<(NE/4 + 255) / 256, 256>>>((const int4*)dst);
    k_scan1<<<SCAN_BLKS, 256>>>();
    k_scan3<<<SCAN_BLKS, 256>>>(x);
    k_fill <<<(NE/4 + 255) / 256, 256>>>((const int4*)src, (const int4*)dst);

    const int g9_blocks  = (NN * 16 + 255) / 256;  // 3125
    const int g64_blocks = (NN * 32 + 255) / 256;  // 6250
    const int gm_blocks  = (NN + GMN - 1) / GMN;   // 782

    // layer 0
    k_gather9<<<g9_blocks, 256>>>();
    k_gemm0f <<<(NN + 7) / 8, 256>>>(W0, b0);
    // layers 1-3
    k_gemm64  <<<gm_blocks, 256>>>(W1);
    k_gather64<false><<<g64_blocks, 256>>>(b1, batch);
    k_gemm64  <<<gm_blocks, 256>>>(W2);
    k_gather64<false><<<g64_blocks, 256>>>(b2, batch);
    k_gemm64  <<<gm_blocks, 256>>>(W3);
    k_gather64<true> <<<g64_blocks, 256>>>(b3, batch);

    k_out<<<(NG*32 + 255) / 256, 256>>>(Wout, bout, out);
}

// round 9
// speedup vs baseline: 1.2719x; 1.0203x over previous
#include <cuda_runtime.h>
#include <cuda_fp16.h>

#define NN 50000
#define NE 800000
#define NG 1024
#define DIN 9
#define DD 64
#define SCAN_BLKS ((NN + 255) / 256)   // 196
#define GMN 64                          // nodes per gemm64 block
#define EPAD (NE + 4*NN)                // padded edge array size

// ---- scratch (static device globals) ----
__device__ __half2  g_h2 [NN*32];        // activations (post-tanh), fp16
__device__ __half2  g_z2 [(NN+1)*32];    // z = dinv * (h @ W), fp16; row NN = 0
__device__ float    g_zx [(NN+1)*16];    // dinv * x, padded to 16; row NN = 0
__device__ float    g_aggx[NN*DIN];      // layer-0 aggregate
__device__ int      g_degi[NN];          // in-degree (no self loop)
__device__ float    g_dinv[NN];
__device__ int      g_rp  [NN];          // padded CSR row start (4-aligned)
__device__ int      g_cur [NN];          // fill cursor
__device__ int      g_es  [EPAD];        // src indices, padded rows -> NN
__device__ int      g_bsum[256];
__device__ unsigned g_gmax[NG*DD];
__device__ float    g_gsum[NG*DD];
__device__ float    g_gcnt[NG];

__device__ __forceinline__ unsigned fkey(float f) {
    unsigned b = __float_as_uint(f);
    return (b & 0x80000000u) ? ~b : (b | 0x80000000u);
}
__device__ __forceinline__ float funkey(unsigned k) {
    unsigned b = (k & 0x80000000u) ? (k & 0x7FFFFFFFu) : ~k;
    return __uint_as_float(b);
}

__global__ void k_init() {
    int i = blockIdx.x * blockDim.x + threadIdx.x;
    if (i < NN) g_degi[i] = 0;
    if (i < NG*DD) { g_gmax[i] = 0u; g_gsum[i] = 0.0f; }
    if (i < NG) g_gcnt[i] = 0.0f;
    if (i < 32) g_z2[NN*32 + i] = __float2half2_rn(0.0f);   // dummy z row
    if (i < 16) g_zx[NN*16 + i] = 0.0f;                     // dummy zx row
}

__global__ void k_deg(const int4* __restrict__ dst4) {
    int e = blockIdx.x * blockDim.x + threadIdx.x;
    if (e >= NE/4) return;
    int4 d = dst4[e];
    atomicAdd(&g_degi[d.x], 1);
    atomicAdd(&g_degi[d.y], 1);
    atomicAdd(&g_degi[d.z], 1);
    atomicAdd(&g_degi[d.w], 1);
}

// shuffle scan of PADDED degree -> rp (exclusive), block sums
__global__ void k_scan1() {
    __shared__ int wsum[8], wpre[8];
    int t = threadIdx.x, i = blockIdx.x * 256 + t;
    int lane = t & 31, w = t >> 5;
    int v = (i < NN) ? ((g_degi[i] + 3) & ~3) : 0;
    int s = v;
    #pragma unroll
    for (int off = 1; off < 32; off <<= 1) {
        int u = __shfl_up_sync(0xFFFFFFFFu, s, off);
        if (lane >= off) s += u;
    }
    if (lane == 31) wsum[w] = s;
    __syncthreads();
    if (t == 0) {
        int a = 0;
        #pragma unroll
        for (int j = 0; j < 8; j++) { wpre[j] = a; a += wsum[j]; }
    }
    __syncthreads();
    int incl = s + wpre[w];
    if (i < NN) g_rp[i] = incl - v;
    if (t == 255) g_bsum[blockIdx.x] = incl;
}

// re-scan bsum + apply; also: cursor, dinv, zx = dinv*x (padded), pad-slot fill
__global__ void k_scan3(const float* __restrict__ x) {
    __shared__ int wsum[8], wpre[8], allincl[256];
    int t = threadIdx.x;
    int lane = t & 31, w = t >> 5;
    int v = (t < SCAN_BLKS) ? g_bsum[t] : 0;
    int s = v;
    #pragma unroll
    for (int off = 1; off < 32; off <<= 1) {
        int u = __shfl_up_sync(0xFFFFFFFFu, s, off);
        if (lane >= off) s += u;
    }
    if (lane == 31) wsum[w] = s;
    __syncthreads();
    if (t == 0) {
        int a = 0;
        #pragma unroll
        for (int j = 0; j < 8; j++) { wpre[j] = a; a += wsum[j]; }
    }
    __syncthreads();
    allincl[t] = s + wpre[w];
    __syncthreads();
    int boff = (blockIdx.x > 0) ? allincl[blockIdx.x - 1] : 0;
    int i = blockIdx.x * 256 + t;
    if (i < NN) {
        int rp = g_rp[i] + boff;
        g_rp[i] = rp;
        g_cur[i] = 0;
        int dg = g_degi[i];
        float dv = rsqrtf(1.0f + (float)dg);
        g_dinv[i] = dv;
        #pragma unroll
        for (int k = 0; k < DIN; k++) g_zx[i*16 + k] = dv * x[i*DIN + k];
        #pragma unroll
        for (int k = DIN; k < 16; k++) g_zx[i*16 + k] = 0.0f;
        int pdg = (dg + 3) & ~3;
        for (int p = dg; p < pdg; p++) g_es[rp + p] = NN;   // pad -> dummy node
    }
}

// 2 int4s per thread: 8 independent atomic->store chains
__global__ void k_fill(const int4* __restrict__ src4, const int4* __restrict__ dst4) {
    int e = blockIdx.x * blockDim.x + threadIdx.x;
    if (e >= NE/8) return;
    int4 s0 = src4[2*e], d0 = dst4[2*e];
    int4 s1 = src4[2*e+1], d1 = dst4[2*e+1];
    g_es[g_rp[d0.x] + atomicAdd(&g_cur[d0.x], 1)] = s0.x;
    g_es[g_rp[d0.y] + atomicAdd(&g_cur[d0.y], 1)] = s0.y;
    g_es[g_rp[d0.z] + atomicAdd(&g_cur[d0.z], 1)] = s0.z;
    g_es[g_rp[d0.w] + atomicAdd(&g_cur[d0.w], 1)] = s0.w;
    g_es[g_rp[d1.x] + atomicAdd(&g_cur[d1.x], 1)] = s1.x;
    g_es[g_rp[d1.y] + atomicAdd(&g_cur[d1.y], 1)] = s1.y;
    g_es[g_rp[d1.z] + atomicAdd(&g_cur[d1.z], 1)] = s1.z;
    g_es[g_rp[d1.w] + atomicAdd(&g_cur[d1.w], 1)] = s1.w;
}

// layer-0: aggx[d] = dinv[d] * (zx[d] + sum zx[s]); 16 lanes/node, padded rows
__global__ void k_gather9() {
    int t = blockIdx.x * blockDim.x + threadIdx.x;
    int n = t >> 4, c = t & 15;
    if (n >= NN) return;
    int rp = g_rp[n];
    int quads = ((g_degi[n] + 3) & ~3) >> 2;
    float a0 = g_zx[n*16 + c], a1 = 0.0f;
    const int4* sp = reinterpret_cast<const int4*>(&g_es[rp]);
    int it = 0;
    for (; it + 2 <= quads; it += 2) {
        int4 s0 = sp[it], s1 = sp[it + 1];
        a0 += g_zx[s0.x*16 + c];
        a1 += g_zx[s0.y*16 + c];
        a0 += g_zx[s0.z*16 + c];
        a1 += g_zx[s0.w*16 + c];
        a0 += g_zx[s1.x*16 + c];
        a1 += g_zx[s1.y*16 + c];
        a0 += g_zx[s1.z*16 + c];
        a1 += g_zx[s1.w*16 + c];
    }
    if (it < quads) {
        int4 s0 = sp[it];
        a0 += g_zx[s0.x*16 + c];
        a1 += g_zx[s0.y*16 + c];
        a0 += g_zx[s0.z*16 + c];
        a1 += g_zx[s0.w*16 + c];
    }
    if (c < DIN) g_aggx[n*DIN + c] = g_dinv[n] * (a0 + a1);
}

// h0 = tanh(aggx @ W0 + b0) -> fp16; 8 nodes/block, lane computes 2 cols
__global__ void k_gemm0f(const float* __restrict__ W, const float* __restrict__ b) {
    __shared__ float Ws[DIN*DD];
    __shared__ float axs[8][DIN];
    int tid = threadIdx.x;
    for (int i = tid; i < DIN*DD; i += 256) Ws[i] = W[i];
    int nb = blockIdx.x * 8;
    if (tid < 8*DIN) {
        int r = tid / DIN, k = tid % DIN, n = nb + r;
        axs[r][k] = (n < NN) ? g_aggx[n*DIN + k] : 0.0f;
    }
    __syncthreads();
    int r = tid >> 5, l = tid & 31;
    int n = nb + r;
    if (n >= NN) return;
    int c0 = 2*l, c1 = 2*l + 1;
    float s0 = b[c0], s1 = b[c1];
    #pragma unroll
    for (int k = 0; k < DIN; k++) {
        float a = axs[r][k];
        s0 += a * Ws[k*DD + c0];
        s1 += a * Ws[k*DD + c1];
    }
    g_h2[n*32 + l] = __floats2half2_rn(tanhf(s0), tanhf(s1));
}

// z = dinv * (h @ W): fp16 storage, fp32 math; 64 nodes/block, 2 rows x 8 cols/thread
__global__ void k_gemm64(const float* __restrict__ W) {
    __shared__ float Ws[DD*DD];
    __shared__ float hs[DD][GMN + 4];
    int tid = threadIdx.x;
    #pragma unroll
    for (int i = 0; i < 16; i++) Ws[tid + i*256] = W[tid + i*256];
    int nb = blockIdx.x * GMN;
    #pragma unroll
    for (int i = 0; i < 8; i++) {
        int idx = tid + i*256;
        int n = idx >> 5, k2 = idx & 31;
        int gn = nb + n;
        float2 f = (gn < NN) ? __half22float2(g_h2[gn*32 + k2])
                             : make_float2(0.0f, 0.0f);
        hs[2*k2    ][n] = f.x;
        hs[2*k2 + 1][n] = f.y;
    }
    __syncthreads();
    int q  = tid & 7;
    int rg = tid >> 3;
    int n0 = 2*rg;
    float acc0[8] = {0,0,0,0,0,0,0,0};
    float acc1[8] = {0,0,0,0,0,0,0,0};
    #pragma unroll
    for (int k = 0; k < DD; k++) {
        float2 h2 = *reinterpret_cast<const float2*>(&hs[k][n0]);
        const float4* wr = reinterpret_cast<const float4*>(&Ws[k*DD + q*8]);
        float4 w0 = wr[0], w1 = wr[1];
        acc0[0] += h2.x*w0.x; acc0[1] += h2.x*w0.y; acc0[2] += h2.x*w0.z; acc0[3] += h2.x*w0.w;
        acc0[4] += h2.x*w1.x; acc0[5] += h2.x*w1.y; acc0[6] += h2.x*w1.z; acc0[7] += h2.x*w1.w;
        acc1[0] += h2.y*w0.x; acc1[1] += h2.y*w0.y; acc1[2] += h2.y*w0.z; acc1[3] += h2.y*w0.w;
        acc1[4] += h2.y*w1.x; acc1[5] += h2.y*w1.y; acc1[6] += h2.y*w1.z; acc1[7] += h2.y*w1.w;
    }
    int gn0 = nb + n0;
    if (gn0 < NN) {
        float dv = g_dinv[gn0];
        __half2 o[4];
        #pragma unroll
        for (int j = 0; j < 4; j++) o[j] = __floats2half2_rn(dv*acc0[2*j], dv*acc0[2*j+1]);
        *reinterpret_cast<uint4*>(&g_z2[gn0*32 + q*4]) = *reinterpret_cast<uint4*>(o);
    }
    if (gn0 + 1 < NN) {
        float dv = g_dinv[gn0 + 1];
        __half2 o[4];
        #pragma unroll
        for (int j = 0; j < 4; j++) o[j] = __floats2half2_rn(dv*acc1[2*j], dv*acc1[2*j+1]);
        *reinterpret_cast<uint4*>(&g_z2[(gn0+1)*32 + q*4]) = *reinterpret_cast<uint4*>(o);
    }
}

// gather: fp16 quad-tree accumulate, fp32 flush per quad; warp-per-node
template <bool POOL>
__global__ void k_gather64(const float* __restrict__ b, const int* __restrict__ batch) {
    int n = (blockIdx.x * blockDim.x + threadIdx.x) >> 5;
    int lane = threadIdx.x & 31;
    if (n >= NN) return;
    int rp = g_rp[n];
    int quads = ((g_degi[n] + 3) & ~3) >> 2;
    float2 self = __half22float2(g_z2[n*32 + lane]);
    float ax = self.x, ay = self.y;
    const int4* sp = reinterpret_cast<const int4*>(&g_es[rp]);
    int it = 0;
    for (; it + 2 <= quads; it += 2) {      // 8 edges in flight
        int4 q0 = sp[it], q1 = sp[it + 1];
        __half2 h0 = g_z2[q0.x*32 + lane];
        __half2 h1 = g_z2[q0.y*32 + lane];
        __half2 h2 = g_z2[q0.z*32 + lane];
        __half2 h3 = g_z2[q0.w*32 + lane];
        __half2 h4 = g_z2[q1.x*32 + lane];
        __half2 h5 = g_z2[q1.y*32 + lane];
        __half2 h6 = g_z2[q1.z*32 + lane];
        __half2 h7 = g_z2[q1.w*32 + lane];
        __half2 sA = __hadd2(__hadd2(h0, h1), __hadd2(h2, h3));   // depth-2 tree
        __half2 sB = __hadd2(__hadd2(h4, h5), __hadd2(h6, h7));
        float2 fA = __half22float2(sA);
        float2 fB = __half22float2(sB);
        ax += fA.x + fB.x;
        ay += fA.y + fB.y;
    }
    if (it < quads) {
        int4 q0 = sp[it];
        __half2 h0 = g_z2[q0.x*32 + lane];
        __half2 h1 = g_z2[q0.y*32 + lane];
        __half2 h2 = g_z2[q0.z*32 + lane];
        __half2 h3 = g_z2[q0.w*32 + lane];
        __half2 sA = __hadd2(__hadd2(h0, h1), __hadd2(h2, h3));
        float2 fA = __half22float2(sA);
        ax += fA.x;
        ay += fA.y;
    }
    float dv = g_dinv[n];
    float2 bb = reinterpret_cast<const float2*>(b)[lane];
    float rx = tanhf(dv*ax + bb.x);
    float ry = tanhf(dv*ay + bb.y);
    g_h2[n*32 + lane] = __floats2half2_rn(rx, ry);
    if (POOL) {
        int g = batch[n];
        int base = g*DD + 2*lane;
        atomicMax(&g_gmax[base + 0], fkey(rx));
        atomicMax(&g_gmax[base + 1], fkey(ry));
        atomicAdd(&g_gsum[base + 0], rx);
        atomicAdd(&g_gsum[base + 1], ry);
        if (lane == 0) atomicAdd(&g_gcnt[g], 1.0f);
    }
}

// warp-per-graph output head
__global__ void k_out(const float* __restrict__ Wout, const float* __restrict__ bout,
                      float* __restrict__ out) {
    int g = (blockIdx.x * blockDim.x + threadIdx.x) >> 5;
    int lane = threadIdx.x & 31;
    if (g >= NG) return;
    float cnt = fmaxf(g_gcnt[g], 1.0f);
    float s = 0.0f;
    #pragma unroll
    for (int d = lane; d < DD; d += 32) {
        s += funkey(g_gmax[g*DD + d]) * Wout[d]
           + (g_gsum[g*DD + d] / cnt) * Wout[DD + d];
    }
    #pragma unroll
    for (int o = 16; o > 0; o >>= 1) s += __shfl_down_sync(0xFFFFFFFFu, s, o);
    if (lane == 0) out[g] = s + bout[0];
}

extern "C" void kernel_launch(void* const* d_in, const int* in_sizes, int n_in,
                              void* d_out, int out_size) {
    const float* x     = (const float*)d_in[0];
    const int*   eidx  = (const int*)  d_in[1];
    const int*   batch = (const int*)  d_in[2];
    const float* W0 = (const float*)d_in[3];  const float* b0 = (const float*)d_in[4];
    const float* W1 = (const float*)d_in[5];  const float* b1 = (const float*)d_in[6];
    const float* W2 = (const float*)d_in[7];  const float* b2 = (const float*)d_in[8];
    const float* W3 = (const float*)d_in[9];  const float* b3 = (const float*)d_in[10];
    const float* Wout = (const float*)d_in[11];
    const float* bout = (const float*)d_in[12];
    float* out = (float*)d_out;

    const int* src = eidx;
    const int* dst = eidx + NE;

    // ---- CSR build (padded rows, index-only edges) ----
    k_init <<<(NG*DD + 255) / 256, 256>>>();
    k_deg  <<<(NE/4 + 255) / 256, 256>>>((const int4*)dst);
    k_scan1<<<SCAN_BLKS, 256>>>();
    k_scan3<<<SCAN_BLKS, 256>>>(x);
    k_fill <<<(NE/8 + 255) / 256, 256>>>((const int4*)src, (const int4*)dst);

    const int g9_blocks  = (NN * 16 + 255) / 256;  // 3125
    const int g64_blocks = (NN * 32 + 255) / 256;  // 6250
    const int gm_blocks  = (NN + GMN - 1) / GMN;   // 782

    // layer 0
    k_gather9<<<g9_blocks, 256>>>();
    k_gemm0f <<<(NN + 7) / 8, 256>>>(W0, b0);
    // layers 1-3
    k_gemm64  <<<gm_blocks, 256>>>(W1);
    k_gather64<false><<<g64_blocks, 256>>>(b1, batch);
    k_gemm64  <<<gm_blocks, 256>>>(W2);
    k_gather64<false><<<g64_blocks, 256>>>(b2, batch);
    k_gemm64  <<<gm_blocks, 256>>>(W3);
    k_gather64<true> <<<g64_blocks, 256>>>(b3, batch);

    k_out<<<(NG*32 + 255) / 256, 256>>>(Wout, bout, out);
}

// round 10
// speedup vs baseline: 2.0161x; 1.5851x over previous
#include <cuda_runtime.h>
#include <cuda_fp16.h>
#include <mma.h>

using namespace nvcuda;

#define NN 50000
#define NE 800000
#define NG 1024
#define DIN 9
#define DD 64
#define SCAN_BLKS ((NN + 255) / 256)   // 196
#define GMN 64                          // nodes per gemm64 block
#define EPAD (NE + 4*NN)                // padded edge array size

// ---- scratch (static device globals) ----
__device__ __half2  g_h2 [NN*32];        // activations (post-tanh), fp16
__device__ __half2  g_z2 [(NN+1)*32];    // z = dinv * (h @ W), fp16; row NN = 0
__device__ float    g_zx [(NN+1)*16];    // dinv * x, padded to 16; row NN = 0
__device__ float    g_aggx[NN*DIN];      // layer-0 aggregate
__device__ int      g_degi[NN];          // in-degree (no self loop)
__device__ float    g_dinv[NN];
__device__ int      g_rp  [NN];          // padded CSR row start (4-aligned)
__device__ int      g_cur [NN];          // fill cursor (pre-seeded with rp)
__device__ int      g_es  [EPAD];        // src indices, padded rows -> NN
__device__ int      g_bsum[256];
__device__ unsigned g_gmax[NG*DD];
__device__ float    g_gsum[NG*DD];
__device__ float    g_gcnt[NG];

__device__ __forceinline__ unsigned fkey(float f) {
    unsigned b = __float_as_uint(f);
    return (b & 0x80000000u) ? ~b : (b | 0x80000000u);
}
__device__ __forceinline__ float funkey(unsigned k) {
    unsigned b = (k & 0x80000000u) ? (k & 0x7FFFFFFFu) : ~k;
    return __uint_as_float(b);
}

__global__ void k_init() {
    int i = blockIdx.x * blockDim.x + threadIdx.x;
    if (i < NN) g_degi[i] = 0;
    if (i < NG*DD) { g_gmax[i] = 0u; g_gsum[i] = 0.0f; }
    if (i < NG) g_gcnt[i] = 0.0f;
    if (i < 32) g_z2[NN*32 + i] = __float2half2_rn(0.0f);   // dummy z row
    if (i < 16) g_zx[NN*16 + i] = 0.0f;                     // dummy zx row
}

__global__ void k_deg(const int4* __restrict__ dst4) {
    int e = blockIdx.x * blockDim.x + threadIdx.x;
    if (e >= NE/4) return;
    int4 d = dst4[e];
    atomicAdd(&g_degi[d.x], 1);
    atomicAdd(&g_degi[d.y], 1);
    atomicAdd(&g_degi[d.z], 1);
    atomicAdd(&g_degi[d.w], 1);
}

// shuffle scan of PADDED degree -> rp (exclusive), block sums
__global__ void k_scan1() {
    __shared__ int wsum[8], wpre[8];
    int t = threadIdx.x, i = blockIdx.x * 256 + t;
    int lane = t & 31, w = t >> 5;
    int v = (i < NN) ? ((g_degi[i] + 3) & ~3) : 0;
    int s = v;
    #pragma unroll
    for (int off = 1; off < 32; off <<= 1) {
        int u = __shfl_up_sync(0xFFFFFFFFu, s, off);
        if (lane >= off) s += u;
    }
    if (lane == 31) wsum[w] = s;
    __syncthreads();
    if (t == 0) {
        int a = 0;
        #pragma unroll
        for (int j = 0; j < 8; j++) { wpre[j] = a; a += wsum[j]; }
    }
    __syncthreads();
    int incl = s + wpre[w];
    if (i < NN) g_rp[i] = incl - v;
    if (t == 255) g_bsum[blockIdx.x] = incl;
}

// re-scan bsum + apply; also: cursor=rp, dinv, zx = dinv*x (padded), pad-slot fill
__global__ void k_scan3(const float* __restrict__ x) {
    __shared__ int wsum[8], wpre[8], allincl[256];
    int t = threadIdx.x;
    int lane = t & 31, w = t >> 5;
    int v = (t < SCAN_BLKS) ? g_bsum[t] : 0;
    int s = v;
    #pragma unroll
    for (int off = 1; off < 32; off <<= 1) {
        int u = __shfl_up_sync(0xFFFFFFFFu, s, off);
        if (lane >= off) s += u;
    }
    if (lane == 31) wsum[w] = s;
    __syncthreads();
    if (t == 0) {
        int a = 0;
        #pragma unroll
        for (int j = 0; j < 8; j++) { wpre[j] = a; a += wsum[j]; }
    }
    __syncthreads();
    allincl[t] = s + wpre[w];
    __syncthreads();
    int boff = (blockIdx.x > 0) ? allincl[blockIdx.x - 1] : 0;
    int i = blockIdx.x * 256 + t;
    if (i < NN) {
        int rp = g_rp[i] + boff;
        g_rp[i] = rp;
        g_cur[i] = rp;                               // cursor starts at row base
        int dg = g_degi[i];
        float dv = rsqrtf(1.0f + (float)dg);
        g_dinv[i] = dv;
        #pragma unroll
        for (int k = 0; k < DIN; k++) g_zx[i*16 + k] = dv * x[i*DIN + k];
        #pragma unroll
        for (int k = DIN; k < 16; k++) g_zx[i*16 + k] = 0.0f;
        int pdg = (dg + 3) & ~3;
        for (int p = dg; p < pdg; p++) g_es[rp + p] = NN;   // pad -> dummy node
    }
}

// 2 int4s per thread: 8 independent atomic->store chains; cur pre-seeded with rp
__global__ void k_fill(const int4* __restrict__ src4, const int4* __restrict__ dst4) {
    int e = blockIdx.x * blockDim.x + threadIdx.x;
    if (e >= NE/8) return;
    int4 s0 = src4[2*e], d0 = dst4[2*e];
    int4 s1 = src4[2*e+1], d1 = dst4[2*e+1];
    g_es[atomicAdd(&g_cur[d0.x], 1)] = s0.x;
    g_es[atomicAdd(&g_cur[d0.y], 1)] = s0.y;
    g_es[atomicAdd(&g_cur[d0.z], 1)] = s0.z;
    g_es[atomicAdd(&g_cur[d0.w], 1)] = s0.w;
    g_es[atomicAdd(&g_cur[d1.x], 1)] = s1.x;
    g_es[atomicAdd(&g_cur[d1.y], 1)] = s1.y;
    g_es[atomicAdd(&g_cur[d1.z], 1)] = s1.z;
    g_es[atomicAdd(&g_cur[d1.w], 1)] = s1.w;
}

// layer-0: aggx[d] = dinv[d] * (zx[d] + sum zx[s]); 16 lanes/node, padded rows
__global__ void k_gather9() {
    int t = blockIdx.x * blockDim.x + threadIdx.x;
    int n = t >> 4, c = t & 15;
    if (n >= NN) return;
    int rp = g_rp[n];
    int quads = ((g_degi[n] + 3) & ~3) >> 2;
    float a0 = g_zx[n*16 + c], a1 = 0.0f;
    const int4* sp = reinterpret_cast<const int4*>(&g_es[rp]);
    int it = 0;
    for (; it + 2 <= quads; it += 2) {
        int4 s0 = sp[it], s1 = sp[it + 1];
        a0 += g_zx[s0.x*16 + c];
        a1 += g_zx[s0.y*16 + c];
        a0 += g_zx[s0.z*16 + c];
        a1 += g_zx[s0.w*16 + c];
        a0 += g_zx[s1.x*16 + c];
        a1 += g_zx[s1.y*16 + c];
        a0 += g_zx[s1.z*16 + c];
        a1 += g_zx[s1.w*16 + c];
    }
    if (it < quads) {
        int4 s0 = sp[it];
        a0 += g_zx[s0.x*16 + c];
        a1 += g_zx[s0.y*16 + c];
        a0 += g_zx[s0.z*16 + c];
        a1 += g_zx[s0.w*16 + c];
    }
    if (c < DIN) g_aggx[n*DIN + c] = g_dinv[n] * (a0 + a1);
}

// h0 = tanh(aggx @ W0 + b0) -> fp16; 8 nodes/block, lane computes 2 cols
__global__ void k_gemm0f(const float* __restrict__ W, const float* __restrict__ b) {
    __shared__ float Ws[DIN*DD];
    __shared__ float axs[8][DIN];
    int tid = threadIdx.x;
    for (int i = tid; i < DIN*DD; i += 256) Ws[i] = W[i];
    int nb = blockIdx.x * 8;
    if (tid < 8*DIN) {
        int r = tid / DIN, k = tid % DIN, n = nb + r;
        axs[r][k] = (n < NN) ? g_aggx[n*DIN + k] : 0.0f;
    }
    __syncthreads();
    int r = tid >> 5, l = tid & 31;
    int n = nb + r;
    if (n >= NN) return;
    int c0 = 2*l, c1 = 2*l + 1;
    float s0 = b[c0], s1 = b[c1];
    #pragma unroll
    for (int k = 0; k < DIN; k++) {
        float a = axs[r][k];
        s0 += a * Ws[k*DD + c0];
        s1 += a * Ws[k*DD + c1];
    }
    g_h2[n*32 + l] = __floats2half2_rn(tanhf(s0), tanhf(s1));
}

// z = dinv * (h @ W) via tensor cores: fp16 in, fp32 acc, fp16 out.
// 64 nodes/block, 8 warps x 2 wmma tiles (16x16), per-warp smem staging epilogue.
#define HP 72   // Hs/Wsh pitch in halfs (mult of 8)
__global__ void k_gemm64(const float* __restrict__ W) {
    __shared__ __half Hs [GMN][HP];      // h tile  [node][k]   9216 B
    __shared__ __half Wsh[DD ][HP];      // W fp16  [k][col]    9216 B
    __shared__ float  stage[8][16][20];  // per-warp epilogue  10240 B
    int tid = threadIdx.x;
    int wid = tid >> 5, lane = tid & 31;
    int nb = blockIdx.x * GMN;

    // load W (fp32 -> fp16), 4 float4 per thread
    #pragma unroll
    for (int i = 0; i < 4; i++) {
        int idx = tid + i*256;               // 0..1023 float4 groups
        float4 f = reinterpret_cast<const float4*>(W)[idx];
        int r = idx >> 4, c0 = (idx & 15) * 4;
        __half2 p0 = __floats2half2_rn(f.x, f.y);
        __half2 p1 = __floats2half2_rn(f.z, f.w);
        *reinterpret_cast<__half2*>(&Wsh[r][c0])     = p0;
        *reinterpret_cast<__half2*>(&Wsh[r][c0 + 2]) = p1;
    }
    // load h tile: 2 uint4 (8 halfs) per thread
    #pragma unroll
    for (int i = 0; i < 2; i++) {
        int idx = tid + i*256;               // 0..511
        int n = idx >> 3, q = idx & 7;
        int gn = nb + n;
        uint4 v = make_uint4(0u, 0u, 0u, 0u);
        if (gn < NN) v = reinterpret_cast<const uint4*>(g_h2)[gn*8 + q];
        *reinterpret_cast<uint4*>(&Hs[n][q*8]) = v;
    }
    __syncthreads();

    wmma::fragment<wmma::matrix_a, 16, 16, 16, __half, wmma::row_major> fa;
    wmma::fragment<wmma::matrix_b, 16, 16, 16, __half, wmma::row_major> fb;

    #pragma unroll
    for (int tt = 0; tt < 2; tt++) {
        int t = wid + tt*8;                  // tile id 0..15
        int tr = t >> 2, tc = t & 3;         // tile row/col in 4x4 grid
        wmma::fragment<wmma::accumulator, 16, 16, 16, float> fc;
        wmma::fill_fragment(fc, 0.0f);
        #pragma unroll
        for (int k0 = 0; k0 < 4; k0++) {
            wmma::load_matrix_sync(fa, &Hs[tr*16][k0*16], HP);
            wmma::load_matrix_sync(fb, &Wsh[k0*16][tc*16], HP);
            wmma::mma_sync(fc, fa, fb, fc);
        }
        wmma::store_matrix_sync(&stage[wid][0][0], fc, 20, wmma::mem_row_major);
        __syncwarp();
        // epilogue: scale by dinv[row], pack half2, store
        #pragma unroll
        for (int e = 0; e < 4; e++) {
            int idx = lane + e*32;           // 0..127
            int r = idx >> 3, c2 = idx & 7;  // row 0..15, half2-col 0..7
            int gn = nb + tr*16 + r;
            if (gn < NN) {
                float dv = g_dinv[gn];
                float f0 = stage[wid][r][c2*2];
                float f1 = stage[wid][r][c2*2 + 1];
                g_z2[gn*32 + tc*8 + c2] = __floats2half2_rn(dv*f0, dv*f1);
            }
        }
        __syncwarp();
    }
}

// gather: fp16 quad-tree accumulate, fp32 flush per quad; warp-per-node
template <bool POOL>
__global__ void k_gather64(const float* __restrict__ b, const int* __restrict__ batch) {
    int n = (blockIdx.x * blockDim.x + threadIdx.x) >> 5;
    int lane = threadIdx.x & 31;
    if (n >= NN) return;
    int rp = g_rp[n];
    int quads = ((g_degi[n] + 3) & ~3) >> 2;
    float2 self = __half22float2(g_z2[n*32 + lane]);
    float ax = self.x, ay = self.y;
    const int4* sp = reinterpret_cast<const int4*>(&g_es[rp]);
    int it = 0;
    for (; it + 2 <= quads; it += 2) {      // 8 edges in flight
        int4 q0 = sp[it], q1 = sp[it + 1];
        __half2 h0 = g_z2[q0.x*32 + lane];
        __half2 h1 = g_z2[q0.y*32 + lane];
        __half2 h2 = g_z2[q0.z*32 + lane];
        __half2 h3 = g_z2[q0.w*32 + lane];
        __half2 h4 = g_z2[q1.x*32 + lane];
        __half2 h5 = g_z2[q1.y*32 + lane];
        __half2 h6 = g_z2[q1.z*32 + lane];
        __half2 h7 = g_z2[q1.w*32 + lane];
        __half2 sA = __hadd2(__hadd2(h0, h1), __hadd2(h2, h3));   // depth-2 tree
        __half2 sB = __hadd2(__hadd2(h4, h5), __hadd2(h6, h7));
        float2 fA = __half22float2(sA);
        float2 fB = __half22float2(sB);
        ax += fA.x + fB.x;
        ay += fA.y + fB.y;
    }
    if (it < quads) {
        int4 q0 = sp[it];
        __half2 h0 = g_z2[q0.x*32 + lane];
        __half2 h1 = g_z2[q0.y*32 + lane];
        __half2 h2 = g_z2[q0.z*32 + lane];
        __half2 h3 = g_z2[q0.w*32 + lane];
        __half2 sA = __hadd2(__hadd2(h0, h1), __hadd2(h2, h3));
        float2 fA = __half22float2(sA);
        ax += fA.x;
        ay += fA.y;
    }
    float dv = g_dinv[n];
    float2 bb = reinterpret_cast<const float2*>(b)[lane];
    float rx = tanhf(dv*ax + bb.x);
    float ry = tanhf(dv*ay + bb.y);
    g_h2[n*32 + lane] = __floats2half2_rn(rx, ry);
    if (POOL) {
        int g = batch[n];
        int base = g*DD + 2*lane;
        atomicMax(&g_gmax[base + 0], fkey(rx));
        atomicMax(&g_gmax[base + 1], fkey(ry));
        atomicAdd(&g_gsum[base + 0], rx);
        atomicAdd(&g_gsum[base + 1], ry);
        if (lane == 0) atomicAdd(&g_gcnt[g], 1.0f);
    }
}

// warp-per-graph output head
__global__ void k_out(const float* __restrict__ Wout, const float* __restrict__ bout,
                      float* __restrict__ out) {
    int g = (blockIdx.x * blockDim.x + threadIdx.x) >> 5;
    int lane = threadIdx.x & 31;
    if (g >= NG) return;
    float cnt = fmaxf(g_gcnt[g], 1.0f);
    float s = 0.0f;
    #pragma unroll
    for (int d = lane; d < DD; d += 32) {
        s += funkey(g_gmax[g*DD + d]) * Wout[d]
           + (g_gsum[g*DD + d] / cnt) * Wout[DD + d];
    }
    #pragma unroll
    for (int o = 16; o > 0; o >>= 1) s += __shfl_down_sync(0xFFFFFFFFu, s, o);
    if (lane == 0) out[g] = s + bout[0];
}

extern "C" void kernel_launch(void* const* d_in, const int* in_sizes, int n_in,
                              void* d_out, int out_size) {
    const float* x     = (const float*)d_in[0];
    const int*   eidx  = (const int*)  d_in[1];
    const int*   batch = (const int*)  d_in[2];
    const float* W0 = (const float*)d_in[3];  const float* b0 = (const float*)d_in[4];
    const float* W1 = (const float*)d_in[5];  const float* b1 = (const float*)d_in[6];
    const float* W2 = (const float*)d_in[7];  const float* b2 = (const float*)d_in[8];
    const float* W3 = (const float*)d_in[9];  const float* b3 = (const float*)d_in[10];
    const float* Wout = (const float*)d_in[11];
    const float* bout = (const float*)d_in[12];
    float* out = (float*)d_out;

    const int* src = eidx;
    const int* dst = eidx + NE;

    // ---- CSR build (padded rows, index-only edges) ----
    k_init <<<(NG*DD + 255) / 256, 256>>>();
    k_deg  <<<(NE/4 + 255) / 256, 256>>>((const int4*)dst);
    k_scan1<<<SCAN_BLKS, 256>>>();
    k_scan3<<<SCAN_BLKS, 256>>>(x);
    k_fill <<<(NE/8 + 255) / 256, 256>>>((const int4*)src, (const int4*)dst);

    const int g9_blocks  = (NN * 16 + 255) / 256;  // 3125
    const int g64_blocks = (NN * 32 + 255) / 256;  // 6250
    const int gm_blocks  = (NN + GMN - 1) / GMN;   // 782

    // layer 0
    k_gather9<<<g9_blocks, 256>>>();
    k_gemm0f <<<(NN + 7) / 8, 256>>>(W0, b0);
    // layers 1-3
    k_gemm64  <<<gm_blocks, 256>>>(W1);
    k_gather64<false><<<g64_blocks, 256>>>(b1, batch);
    k_gemm64  <<<gm_blocks, 256>>>(W2);
    k_gather64<false><<<g64_blocks, 256>>>(b2, batch);
    k_gemm64  <<<gm_blocks, 256>>>(W3);
    k_gather64<true> <<<g64_blocks, 256>>>(b3, batch);

    k_out<<<(NG*32 + 255) / 256, 256>>>(Wout, bout, out);
}